// round 10
// baseline (speedup 1.0000x reference)
#include <cuda_runtime.h>

typedef unsigned long long u64;

__device__ __forceinline__ u64 pk2(float lo, float hi){
  u64 r; asm volatile("mov.b64 %0, {%1,%2};" : "=l"(r) : "f"(lo), "f"(hi)); return r;
}
__device__ __forceinline__ void upk2(u64 v, float& lo, float& hi){
  asm("mov.b64 {%0,%1}, %2;" : "=f"(lo), "=f"(hi) : "l"(v));
}
__device__ __forceinline__ u64 fma2(u64 a, u64 b, u64 c){
  u64 d; asm("fma.rn.f32x2 %0, %1, %2, %3;" : "=l"(d) : "l"(a), "l"(b), "l"(c)); return d;
}
__device__ __forceinline__ u64 mul2(u64 a, u64 b){
  u64 d; asm("mul.rn.f32x2 %0, %1, %2;" : "=l"(d) : "l"(a), "l"(b)); return d;
}
__device__ __forceinline__ u64 add2(u64 a, u64 b){
  u64 d; asm("add.rn.f32x2 %0, %1, %2;" : "=l"(d) : "l"(a), "l"(b)); return d;
}

// 8 rows per CTA stored as 4 row-pairs (u64 packs 2 rows). Per position: two
// 16B slots, slot g holds pairs {2g, 2g+1}. Slot select
// sigma = (g ^ (p>>2) ^ (p>>5)) & 1, plus 32B padding every 8 positions.
// Bank-enumerated: conflict-free for P1 stores (p stride 8) and P2 r/w
// (p stride 1); P3 LDS.64 reads are 2-way (per-byte cost == conflict-free
// LDS.128 — accepted).
__device__ __forceinline__ int fidx(int pos, int g){
  return (pos << 3) + ((pos >> 3) << 3)
       + ((((pos >> 2) ^ (pos >> 5) ^ g) & 1) << 2);
}

// Butterfly on one pair of positions for 4 rows (2 packed f32x2 lanes each).
__device__ __forceinline__ void bflyq(u64& x0a, u64& x0b, u64& x1a, u64& x1b,
                                      float4 t){
  u64 m0 = pk2(t.x, t.x);
  u64 m1 = pk2(t.y, t.y);
  u64 m2 = pk2(t.z, t.z);
  u64 m3 = pk2(t.w, t.w);
  u64 a = x0a, b = x1a;
  x0a = fma2(m0, a, mul2(m1, b));
  x1a = fma2(m2, a, mul2(m3, b));
  a = x0b; b = x1b;
  x0b = fma2(m0, a, mul2(m1, b));
  x1b = fma2(m2, a, mul2(m3, b));
}

// Butterfly on one pair of positions for 2 rows (one packed f32x2 lane).
__device__ __forceinline__ void bfly1(u64& x0, u64& x1, float4 t){
  u64 m0 = pk2(t.x, t.x);
  u64 m1 = pk2(t.y, t.y);
  u64 m2 = pk2(t.z, t.z);
  u64 m3 = pk2(t.w, t.w);
  u64 a = x0, b = x1;
  x0 = fma2(m0, a, mul2(m1, b));
  x1 = fma2(m2, a, mul2(m3, b));
}

// Data tile: 8 rows, padded layout -> 9216 floats (36KB).
// Padded stage0-2 twiddle stash (R9): float4 pp of stage s at float offset
// TWF + s*2560 + 4*pp + 4*(pp>>2) -> consumer reads at 20*o + immediates,
// conflict-free.
#define TWF 9216
#define TWS 2560

__global__ __launch_bounds__(256, 3)
void butterfly_kernel(const float* __restrict__ x,
                      const float* __restrict__ twg,
                      const float* __restrict__ bias,
                      float* __restrict__ out)
{
  extern __shared__ float sdata[];
  const float4* tw4 = (const float4*)twg;
  const int tid = threadIdx.x;

  // ---- Stage the stage-0..2 twiddles coalesced into the padded stash ----
  #pragma unroll
  for (int i = 0; i < 6; i++){
    int p  = tid + 256 * i;
    float4 t = tw4[p];
    int s  = p >> 9;
    int pp = p & 511;
    *(float4*)&sdata[TWF + s * TWS + 4 * pp + 4 * (pp >> 2)] = t;
  }

  const int o   = tid & 127;         // position-octet index (P1/P2)
  const int sub = tid >> 7;          // quad (4 rows) 0/1 (P1/P2)
  const long long row0 = (long long)blockIdx.x * 8 + sub * 4;

  // ---- x loads first (overlap with stash fill, before the barrier) ----
  const float* base = x + row0 * 1024 + 8 * o;
  float4 a0 = *(const float4*)(base        );
  float4 b0 = *(const float4*)(base +    4 );
  float4 a1 = *(const float4*)(base + 1024 );
  float4 b1 = *(const float4*)(base + 1028 );
  float4 a2 = *(const float4*)(base + 2048 );
  float4 b2 = *(const float4*)(base + 2052 );
  float4 a3 = *(const float4*)(base + 3072 );
  float4 b3 = *(const float4*)(base + 3076 );
  u64 v01[8], v23[8];
  v01[0]=pk2(a0.x,a1.x); v01[1]=pk2(a0.y,a1.y); v01[2]=pk2(a0.z,a1.z); v01[3]=pk2(a0.w,a1.w);
  v01[4]=pk2(b0.x,b1.x); v01[5]=pk2(b0.y,b1.y); v01[6]=pk2(b0.z,b1.z); v01[7]=pk2(b0.w,b1.w);
  v23[0]=pk2(a2.x,a3.x); v23[1]=pk2(a2.y,a3.y); v23[2]=pk2(a2.z,a3.z); v23[3]=pk2(a2.w,a3.w);
  v23[4]=pk2(b2.x,b3.x); v23[5]=pk2(b2.y,b3.y); v23[6]=pk2(b2.z,b3.z); v23[7]=pk2(b2.w,b3.w);

  __syncthreads();   // stash ready

  // ================= PASS 1: stages 0-2 (stride 1,2,4) =====================
  // Twiddles level-by-level from the stash (16 floats live at a time).
  {
    const float* tb = &sdata[TWF + 20 * o];
    #pragma unroll
    for (int i = 0; i < 4; i++)   // stage 0: pairs (2i, 2i+1)
      bflyq(v01[2*i], v23[2*i], v01[2*i+1], v23[2*i+1],
            *(const float4*)&tb[0 * TWS + 4 * i]);
    #pragma unroll
    for (int i = 0; i < 4; i++){  // stage 1: pairs (0,2)(1,3)(4,6)(5,7)
      const int a = (i & 1) + 4 * (i >> 1);
      bflyq(v01[a], v23[a], v01[a+2], v23[a+2],
            *(const float4*)&tb[1 * TWS + 4 * i]);
    }
    #pragma unroll
    for (int i = 0; i < 4; i++)   // stage 2: pairs (i, i+4)
      bflyq(v01[i], v23[i], v01[i+4], v23[i+4],
            *(const float4*)&tb[2 * TWS + 4 * i]);
    #pragma unroll
    for (int c = 0; c < 8; c++){
      ulonglong2 u; u.x = v01[c]; u.y = v23[c];
      *(ulonglong2*)&sdata[fidx(8 * o + c, sub)] = u;
    }
  }
  __syncthreads();

  // ================= PASS 2: stages 3-5 (stride 8,16,32) ===================
  {
    const int bb = o >> 3, j = o & 7;
    #pragma unroll
    for (int k = 0; k < 8; k++){
      ulonglong2 u = *(ulonglong2*)&sdata[fidx(64 * bb + 8 * k + j, sub)];
      v01[k] = u.x; v23[k] = u.y;
    }
    #pragma unroll
    for (int i = 0; i < 4; i++)   // stage 3: pairs (2i, 2i+1)
      bflyq(v01[2*i], v23[2*i], v01[2*i+1], v23[2*i+1],
            tw4[3 * 512 + 32 * bb + j + 8 * i]);
    #pragma unroll
    for (int i = 0; i < 4; i++){  // stage 4: pairs (0,2)(1,3)(4,6)(5,7)
      const int a = (i & 1) + 4 * (i >> 1);
      bflyq(v01[a], v23[a], v01[a+2], v23[a+2],
            tw4[4 * 512 + 32 * bb + j + 8 * i]);
    }
    #pragma unroll
    for (int i = 0; i < 4; i++)   // stage 5: pairs (i, i+4)
      bflyq(v01[i], v23[i], v01[i+4], v23[i+4],
            tw4[5 * 512 + 32 * bb + j + 8 * i]);
    #pragma unroll
    for (int k = 0; k < 8; k++){
      ulonglong2 u; u.x = v01[k]; u.y = v23[k];
      *(ulonglong2*)&sdata[fidx(64 * bb + 8 * k + j, sub)] = u;
    }
  }
  __syncthreads();

  // ====== PASS 3: stages 6-9 (stride 64,128,256,512) + bias -> global ======
  // Thread owns row-pair pr for positions j2 + 64m, m=0..15 (16 u64 regs).
  {
    const int j2 = tid & 63;
    const int pr = tid >> 6;          // row-pair 0..3
    const int g  = pr >> 1;
    const int h  = (pr & 1) << 1;     // float offset within the 16B slot
    u64 v[16];
    #pragma unroll
    for (int m = 0; m < 16; m++)
      v[m] = *(const u64*)&sdata[fidx(j2 + 64 * m, g) + h];

    #pragma unroll
    for (int r = 0; r < 8; r++)       // stage 6: pairs (2r, 2r+1)
      bfly1(v[2*r], v[2*r+1], tw4[6 * 512 + 64 * r + j2]);
    #pragma unroll
    for (int r = 0; r < 4; r++)       // stage 7: pairs (4r+hh, 4r+hh+2)
      #pragma unroll
      for (int hh = 0; hh < 2; hh++)
        bfly1(v[4*r+hh], v[4*r+hh+2], tw4[7 * 512 + 128 * r + 64 * hh + j2]);
    #pragma unroll
    for (int r = 0; r < 2; r++)       // stage 8: pairs (8r+hh, 8r+hh+4)
      #pragma unroll
      for (int hh = 0; hh < 4; hh++)
        bfly1(v[8*r+hh], v[8*r+hh+4], tw4[8 * 512 + 256 * r + 64 * hh + j2]);
    #pragma unroll
    for (int hh = 0; hh < 8; hh++)    // stage 9: pairs (hh, hh+8)
      bfly1(v[hh], v[hh+8], tw4[9 * 512 + 64 * hh + j2]);

    // bias + store (lanes j2 consecutive -> coalesced STG.32)
    const long long r0 = (long long)blockIdx.x * 8 + 2 * pr;
    float* obase = out + r0 * 1024 + j2;
    #pragma unroll
    for (int m = 0; m < 16; m++){
      float b = bias[j2 + 64 * m];
      u64 y = add2(v[m], pk2(b, b));
      float f0, f1;
      upk2(y, f0, f1);
      float* op = obase + 64 * m;
      op[0]    = f0;
      op[1024] = f1;
    }
  }
}

extern "C" void kernel_launch(void* const* d_in, const int* in_sizes, int n_in,
                              void* d_out, int out_size)
{
  const float* x    = (const float*)d_in[0];   // (32768, 1024) f32
  const float* tw   = (const float*)d_in[1];   // (1, 10, 512, 2, 2) f32
  const float* bias = (const float*)d_in[2];   // (1024,) f32
  float* out = (float*)d_out;                  // (32768, 1024) f32

  const int batch = in_sizes[0] / 1024;
  const int smem_bytes = (TWF + 3 * TWS) * 4;  // 36KB data + 30KB tw stash

  cudaFuncSetAttribute(butterfly_kernel,
                       cudaFuncAttributeMaxDynamicSharedMemorySize, smem_bytes);
  butterfly_kernel<<<batch / 8, 256, smem_bytes>>>(x, tw, bias, out);
}